// round 14
// baseline (speedup 1.0000x reference)
#include <cuda_runtime.h>
#include <cuda_bf16.h>
#include <cstdint>

// ============================================================================
// SSIM loss, separable Gaussian, 4-signal (u=x+y, v=x-y), bf16-staged smem,
// FFMA-imm convolution. R14 = R5 arithmetic, software-pipelined phases:
// load(ch+1) overlaps v-pass(ch); 6 barriers instead of 9.
// ============================================================================

static constexpr int THREADS = 384;
static constexpr int NBLK    = 2048;
static constexpr float C1 = 1.0e-4f;
static constexpr float C2 = 9.0e-4f;

__device__ constexpr float G[11] = {
    0.00102840f, 0.00759878f, 0.03600077f, 0.10936042f, 0.21300560f,
    0.26601170f,
    0.21300560f, 0.10936042f, 0.03600077f, 0.00759878f, 0.00102840f
};

struct SmemLayout {
    uint32_t plane[64][67];     // bf16x2 (hi=v, lo=u)            17,152 B
    uint32_t hpq[64][55];       // bf16x2 (hi=q,  lo=p)           14,080 B
    uint32_t hs [64][55];       // bf16x2 (hi=sv, lo=su)          14,080 B
    float red[THREADS / 32];
    unsigned int ticket;
};
static constexpr int SMEM_BYTES = (int)sizeof(SmemLayout);   // ~45.4 KB

__device__ float        g_part[NBLK];
__device__ unsigned int g_count = 0;

__device__ __forceinline__ uint32_t pk(float hi, float lo) {
    uint32_t r;
    asm("cvt.rn.bf16x2.f32 %0, %1, %2;" : "=r"(r) : "f"(hi), "f"(lo));
    return r;
}
__device__ __forceinline__ float lo_f(uint32_t w) { return __uint_as_float(w << 16); }
__device__ __forceinline__ float hi_f(uint32_t w) { return __uint_as_float(w & 0xFFFF0000u); }

// ---- phase bodies (inlined) ------------------------------------------------

__device__ __forceinline__ void load_plane(SmemLayout& s, const float* pb,
                                           const float* gb, int ch, int tid)
{
    for (int i = tid; i < 4096; i += THREADS) {
        const float x = pb[i * 3 + ch];
        const float y = gb[i * 3 + ch];
        s.plane[i >> 6][i & 63] = pk(x - y, x + y);   // hi=v, lo=u
    }
}

__device__ __forceinline__ void h_pass(SmemLayout& s, int tid)
{
    const int seg = tid / 64;
    const int r   = tid & 63;
    const int c0  = seg * 9;

    float a0[9] = {}, a1[9] = {}, a2[9] = {}, a3[9] = {};
    #pragma unroll
    for (int j = 0; j < 19; ++j) {
        const uint32_t w = s.plane[r][c0 + j];
        const float u = lo_f(w), v = hi_f(w);
        const float uu = u * u, vv = v * v;
        #pragma unroll
        for (int k = 0; k < 11; ++k) {
            const int o = j - k;                 // compile-time pruned
            if (o >= 0 && o < 9) {
                a0[o] = fmaf(u,  G[k], a0[o]);   // FFMA-imm
                a1[o] = fmaf(v,  G[k], a1[o]);
                a2[o] = fmaf(uu, G[k], a2[o]);
                a3[o] = fmaf(vv, G[k], a3[o]);
            }
        }
    }
    #pragma unroll
    for (int o = 0; o < 9; ++o) {
        s.hpq[r][c0 + o] = pk(a1[o], a0[o]);     // hi=q,  lo=p
        s.hs [r][c0 + o] = pk(a3[o], a2[o]);     // hi=sv, lo=su
    }
}

__device__ __forceinline__ void v_pass(SmemLayout& s, int tid, float& local)
{
    if (tid >= 324) return;
    const int c  = tid % 54;
    const int r0 = (tid / 54) * 9;

    float a0[9] = {}, a1[9] = {}, a2[9] = {}, a3[9] = {};
    #pragma unroll
    for (int j = 0; j < 19; ++j) {
        const uint32_t wpq = s.hpq[r0 + j][c];
        const uint32_t ws  = s.hs [r0 + j][c];
        const float p  = lo_f(wpq), q  = hi_f(wpq);
        const float su = lo_f(ws),  sv = hi_f(ws);
        #pragma unroll
        for (int k = 0; k < 11; ++k) {
            const int o = j - k;
            if (o >= 0 && o < 9) {
                a0[o] = fmaf(p,  G[k], a0[o]);
                a1[o] = fmaf(q,  G[k], a1[o]);
                a2[o] = fmaf(su, G[k], a2[o]);
                a3[o] = fmaf(sv, G[k], a3[o]);
            }
        }
    }
    #pragma unroll
    for (int o = 0; o < 9; ++o) {
        const float p = a0[o], q = a1[o];
        const float P = p * p, Q = q * q;
        const float A = 0.5f * (P - Q);          // 2*mu1*mu2
        const float B = 0.5f * (P + Q);          // mu1^2 + mu2^2
        const float num = (A + C1) * (fmaf(0.5f, a2[o] - a3[o], C2) - A);
        const float den = (B + C1) * (fmaf(0.5f, a2[o] + a3[o], C2) - B);
        local += __fdividef(num, den);
    }
}

__global__ __launch_bounds__(THREADS, 3)
void ssim_main(const float* __restrict__ pred, const float* __restrict__ gt,
               float* __restrict__ out)
{
    extern __shared__ unsigned char smem_raw[];
    SmemLayout& s = *reinterpret_cast<SmemLayout*>(smem_raw);

    const int tid  = threadIdx.x;
    const int warp = tid >> 5;
    const int lane = tid & 31;
    const float* pb = pred + (size_t)blockIdx.x * 12288;
    const float* gb = gt   + (size_t)blockIdx.x * 12288;

    float local = 0.0f;

    // ---- software pipeline: 6 barriers total ------------------------------
    load_plane(s, pb, gb, 0, tid);
    __syncthreads();                    // plane(0) ready
    h_pass(s, tid);
    __syncthreads();                    // hb(0) ready, plane free

    #pragma unroll
    for (int ch = 0; ch < 3; ++ch) {
        if (ch < 2) load_plane(s, pb, gb, ch + 1, tid);  // LDGs issue early
        v_pass(s, tid, local);                           // overlaps LDG latency
        __syncthreads();                // hb free, plane(ch+1) ready
        if (ch < 2) {
            h_pass(s, tid);
            __syncthreads();            // hb(ch+1) ready, plane free
        }
    }

    // ---- fixed-order block reduction --------------------------------------
    #pragma unroll
    for (int off = 16; off > 0; off >>= 1)
        local += __shfl_down_sync(0xffffffffu, local, off);
    if (lane == 0) s.red[warp] = local;
    __syncthreads();
    if (tid == 0) {
        float sum = 0.0f;
        #pragma unroll
        for (int w = 0; w < THREADS / 32; ++w) sum += s.red[w];
        g_part[blockIdx.x] = sum;
        __threadfence();
        s.ticket = atomicAdd(&g_count, 1u);
    }
    __syncthreads();

    // ---- last block: deterministic global reduction -----------------------
    if (s.ticket == NBLK - 1) {
        float sum = 0.0f;
        for (int i = tid; i < NBLK; i += THREADS) sum += g_part[i];
        #pragma unroll
        for (int off = 16; off > 0; off >>= 1)
            sum += __shfl_down_sync(0xffffffffu, sum, off);
        if (lane == 0) s.red[warp] = sum;
        __syncthreads();
        if (tid == 0) {
            float t = 0.0f;
            #pragma unroll
            for (int w = 0; w < THREADS / 32; ++w) t += s.red[w];
            out[0] = 1.0f - t * (1.0f / 17915904.0f);   // 2048*3*54*54
            g_count = 0;                                 // reset for replay
        }
    }
}

extern "C" void kernel_launch(void* const* d_in, const int* in_sizes, int n_in,
                              void* d_out, int out_size)
{
    const float* pred = (const float*)d_in[0];
    const float* gt   = (const float*)d_in[1];
    float* out        = (float*)d_out;

    cudaFuncSetAttribute(ssim_main, cudaFuncAttributeMaxDynamicSharedMemorySize,
                         SMEM_BYTES);
    ssim_main<<<NBLK, THREADS, SMEM_BYTES>>>(pred, gt, out);
}

// round 15
// speedup vs baseline: 1.1963x; 1.1963x over previous
#include <cuda_runtime.h>
#include <cuda_bf16.h>
#include <cstdint>

// ============================================================================
// SSIM loss, separable Gaussian, 4-signal (u=x+y, v=x-y), bf16-staged smem,
// f32x2 packed convolution (halved issue slots), 3 CTAs/SM.
// Two sweeps per pass keep live registers under the 56-reg cap.
// ============================================================================

static constexpr int THREADS = 384;
static constexpr int NBLK    = 2048;
static constexpr float C1 = 1.0e-4f;
static constexpr float C2 = 9.0e-4f;

__device__ constexpr float G[11] = {
    0.00102840f, 0.00759878f, 0.03600077f, 0.10936042f, 0.21300560f,
    0.26601170f,
    0.21300560f, 0.10936042f, 0.03600077f, 0.00759878f, 0.00102840f
};

struct SmemLayout {
    uint32_t plane[64][67];     // bf16x2 (hi=v, lo=u)            17,152 B
    uint32_t hpq[64][55];       // bf16x2 (hi=q,  lo=p)           14,080 B
    uint32_t hs [64][55];       // bf16x2 (hi=sv, lo=su)          14,080 B
    float red[THREADS / 32];
    unsigned int ticket;
};
static constexpr int SMEM_BYTES = (int)sizeof(SmemLayout);   // ~45.4 KB

__device__ float        g_part[NBLK];
__device__ unsigned int g_count = 0;

typedef unsigned long long u64;

__device__ __forceinline__ uint32_t pk(float hi, float lo) {
    uint32_t r;
    asm("cvt.rn.bf16x2.f32 %0, %1, %2;" : "=r"(r) : "f"(hi), "f"(lo));
    return r;
}
// bf16x2 word -> packed f32x2 (lo lane = low bf16, hi lane = high bf16)
__device__ __forceinline__ u64 up2(uint32_t w) {
    u64 r;
    const uint32_t lo = w << 16;
    const uint32_t hi = w & 0xFFFF0000u;
    asm("mov.b64 %0, {%1, %2};" : "=l"(r) : "r"(lo), "r"(hi));
    return r;
}
__device__ __forceinline__ u64 pack2(float lo, float hi) {
    u64 r;
    asm("mov.b64 %0, {%1, %2};" : "=l"(r) : "f"(lo), "f"(hi));
    return r;
}
__device__ __forceinline__ void unpack2(u64 p, float& lo, float& hi) {
    asm("mov.b64 {%0, %1}, %2;" : "=f"(lo), "=f"(hi) : "l"(p));
}
__device__ __forceinline__ u64 fma2(u64 a, u64 b, u64 c) {
    u64 d;
    asm("fma.rn.f32x2 %0, %1, %2, %3;" : "=l"(d) : "l"(a), "l"(b), "l"(c));
    return d;
}
__device__ __forceinline__ u64 mul2(u64 a, u64 b) {
    u64 d;
    asm("mul.rn.f32x2 %0, %1, %2;" : "=l"(d) : "l"(a), "l"(b));
    return d;
}

__global__ __launch_bounds__(THREADS, 3)
void ssim_main(const float* __restrict__ pred, const float* __restrict__ gt,
               float* __restrict__ out)
{
    extern __shared__ unsigned char smem_raw[];
    SmemLayout& s = *reinterpret_cast<SmemLayout*>(smem_raw);

    const int tid  = threadIdx.x;
    const int warp = tid >> 5;
    const int lane = tid & 31;
    const float* pb = pred + (size_t)blockIdx.x * 12288;
    const float* gb = gt   + (size_t)blockIdx.x * 12288;

    // 6 distinct packed weights (Gaussian symmetry G[k] = G[10-k])
    u64 W6[6];
    #pragma unroll
    for (int k = 0; k < 6; ++k) W6[k] = pack2(G[k], G[k]);

    float local = 0.0f;

    for (int ch = 0; ch < 3; ++ch) {
        __syncthreads();

        // ---- load channel plane, pack (u,v) = (x+y, x-y) as bf16x2 --------
        for (int i = tid; i < 4096; i += THREADS) {
            const float x = pb[i * 3 + ch];
            const float y = gb[i * 3 + ch];
            s.plane[i >> 6][i & 63] = pk(x - y, x + y);   // hi=v, lo=u
        }
        __syncthreads();

        // ---- horizontal pass: seg=tid/64 (6 segs x 9 cols), r=tid%64 ------
        {
            const int seg = tid / 64;
            const int r   = tid & 63;
            const int c0  = seg * 9;

            // sweep 1: (u, v)
            {
                u64 acc[9];
                #pragma unroll
                for (int o = 0; o < 9; ++o) acc[o] = 0ull;
                #pragma unroll
                for (int j = 0; j < 19; ++j) {
                    const u64 uv = up2(s.plane[r][c0 + j]);
                    #pragma unroll
                    for (int k = 0; k < 11; ++k) {
                        const int o = j - k;             // compile-time pruned
                        if (o >= 0 && o < 9)
                            acc[o] = fma2(W6[k < 6 ? k : 10 - k], uv, acc[o]);
                    }
                }
                #pragma unroll
                for (int o = 0; o < 9; ++o) {
                    float p, q;
                    unpack2(acc[o], p, q);
                    s.hpq[r][c0 + o] = pk(q, p);         // hi=q, lo=p
                }
            }
            // sweep 2: (u^2, v^2)
            {
                u64 acc[9];
                #pragma unroll
                for (int o = 0; o < 9; ++o) acc[o] = 0ull;
                #pragma unroll
                for (int j = 0; j < 19; ++j) {
                    const u64 uv = up2(s.plane[r][c0 + j]);
                    const u64 sq = mul2(uv, uv);
                    #pragma unroll
                    for (int k = 0; k < 11; ++k) {
                        const int o = j - k;
                        if (o >= 0 && o < 9)
                            acc[o] = fma2(W6[k < 6 ? k : 10 - k], sq, acc[o]);
                    }
                }
                #pragma unroll
                for (int o = 0; o < 9; ++o) {
                    float su, sv;
                    unpack2(acc[o], su, sv);
                    s.hs[r][c0 + o] = pk(sv, su);        // hi=sv, lo=su
                }
            }
        }
        __syncthreads();

        // ---- vertical pass + ssim: 324 tasks = 6 row-segs x 54 cols -------
        if (tid < 324) {
            const int c  = tid % 54;
            const int r0 = (tid / 54) * 9;

            u64 apq[9];
            #pragma unroll
            for (int o = 0; o < 9; ++o) apq[o] = 0ull;
            #pragma unroll
            for (int j = 0; j < 19; ++j) {
                const u64 pq = up2(s.hpq[r0 + j][c]);
                #pragma unroll
                for (int k = 0; k < 11; ++k) {
                    const int o = j - k;
                    if (o >= 0 && o < 9)
                        apq[o] = fma2(W6[k < 6 ? k : 10 - k], pq, apq[o]);
                }
            }
            u64 asq[9];
            #pragma unroll
            for (int o = 0; o < 9; ++o) asq[o] = 0ull;
            #pragma unroll
            for (int j = 0; j < 19; ++j) {
                const u64 sq = up2(s.hs[r0 + j][c]);
                #pragma unroll
                for (int k = 0; k < 11; ++k) {
                    const int o = j - k;
                    if (o >= 0 && o < 9)
                        asq[o] = fma2(W6[k < 6 ? k : 10 - k], sq, asq[o]);
                }
            }
            #pragma unroll
            for (int o = 0; o < 9; ++o) {
                float p, q, su, sv;
                unpack2(apq[o], p, q);
                unpack2(asq[o], su, sv);
                const float P = p * p, Q = q * q;
                const float A = 0.5f * (P - Q);          // 2*mu1*mu2
                const float B = 0.5f * (P + Q);          // mu1^2 + mu2^2
                const float num = (A + C1) * (fmaf(0.5f, su - sv, C2) - A);
                const float den = (B + C1) * (fmaf(0.5f, su + sv, C2) - B);
                local += __fdividef(num, den);
            }
        }
    }

    // ---- fixed-order block reduction --------------------------------------
    __syncthreads();
    #pragma unroll
    for (int off = 16; off > 0; off >>= 1)
        local += __shfl_down_sync(0xffffffffu, local, off);
    if (lane == 0) s.red[warp] = local;
    __syncthreads();
    if (tid == 0) {
        float sum = 0.0f;
        #pragma unroll
        for (int w = 0; w < THREADS / 32; ++w) sum += s.red[w];
        g_part[blockIdx.x] = sum;
        __threadfence();
        s.ticket = atomicAdd(&g_count, 1u);
    }
    __syncthreads();

    // ---- last block: deterministic global reduction -----------------------
    if (s.ticket == NBLK - 1) {
        float sum = 0.0f;
        for (int i = tid; i < NBLK; i += THREADS) sum += g_part[i];
        #pragma unroll
        for (int off = 16; off > 0; off >>= 1)
            sum += __shfl_down_sync(0xffffffffu, sum, off);
        if (lane == 0) s.red[warp] = sum;
        __syncthreads();
        if (tid == 0) {
            float t = 0.0f;
            #pragma unroll
            for (int w = 0; w < THREADS / 32; ++w) t += s.red[w];
            out[0] = 1.0f - t * (1.0f / 17915904.0f);   // 2048*3*54*54
            g_count = 0;                                 // reset for replay
        }
    }
}

extern "C" void kernel_launch(void* const* d_in, const int* in_sizes, int n_in,
                              void* d_out, int out_size)
{
    const float* pred = (const float*)d_in[0];
    const float* gt   = (const float*)d_in[1];
    float* out        = (float*)d_out;

    cudaFuncSetAttribute(ssim_main, cudaFuncAttributeMaxDynamicSharedMemorySize,
                         SMEM_BYTES);
    ssim_main<<<NBLK, THREADS, SMEM_BYTES>>>(pred, gt, out);
}